// round 6
// baseline (speedup 1.0000x reference)
#include <cuda_runtime.h>
#include <cstdint>

// Fixed problem shape (GroupFC): h[B,G,D], W[G,D,K], out[B,G,K]
#define B_SZ 256
#define G_SZ 100
#define D_SZ 768
#define K_SZ 128

// Scratch for reciprocal norms (device globals: allocation-free per harness rules)
__device__ float g_rinvH[B_SZ * G_SZ];   // 1/max(||h[b,g,:]||, eps)
__device__ float g_rinvW[G_SZ * K_SZ];   // 1/max(||W[g,:,k]||, eps)

// ---------------------------------------------------------------------------
// Kernel 1: h row norms. One warp per (b,g) row of length D=768 (contiguous).
// ---------------------------------------------------------------------------
__global__ void hnorm_kernel(const float* __restrict__ h) {
    int warp = (blockIdx.x * blockDim.x + threadIdx.x) >> 5;
    int lane = threadIdx.x & 31;
    if (warp >= B_SZ * G_SZ) return;
    const float4* row = reinterpret_cast<const float4*>(h + (size_t)warp * D_SZ);
    float s = 0.f;
#pragma unroll
    for (int i = 0; i < 6; i++) {              // 6 * 32 * 4 = 768
        float4 v = row[lane + i * 32];
        s = fmaf(v.x, v.x, fmaf(v.y, v.y, fmaf(v.z, v.z, fmaf(v.w, v.w, s))));
    }
#pragma unroll
    for (int o = 16; o; o >>= 1) s += __shfl_xor_sync(0xffffffffu, s, o);
    if (lane == 0) g_rinvH[warp] = 1.0f / fmaxf(sqrtf(s), 1e-12f);
}

// ---------------------------------------------------------------------------
// Kernel 2: W column norms over d (stride K). One block per group g,
// 512 threads = 4 d-chunks x 128 k. Loads are coalesced over k.
// ---------------------------------------------------------------------------
__global__ void wnorm_kernel(const float* __restrict__ w) {
    __shared__ float partial[4][K_SZ];
    int g = blockIdx.x;
    int k = threadIdx.x & 127;
    int c = threadIdx.x >> 7;                  // 0..3, each covers 192 d's
    const float* base = w + ((size_t)g * D_SZ + (size_t)c * 192) * K_SZ + k;
    float s0 = 0.f, s1 = 0.f, s2 = 0.f, s3 = 0.f;
#pragma unroll 4
    for (int d = 0; d < 192; d += 4) {
        float v0 = base[(size_t)(d + 0) * K_SZ];
        float v1 = base[(size_t)(d + 1) * K_SZ];
        float v2 = base[(size_t)(d + 2) * K_SZ];
        float v3 = base[(size_t)(d + 3) * K_SZ];
        s0 = fmaf(v0, v0, s0); s1 = fmaf(v1, v1, s1);
        s2 = fmaf(v2, v2, s2); s3 = fmaf(v3, v3, s3);
    }
    partial[c][k] = (s0 + s1) + (s2 + s3);
    __syncthreads();
    if (threadIdx.x < K_SZ) {
        float s = partial[0][k] + partial[1][k] + partial[2][k] + partial[3][k];
        g_rinvW[g * K_SZ + k] = 1.0f / fmaxf(sqrtf(s), 1e-12f);
    }
}

// ---------------------------------------------------------------------------
// Kernel 3: grouped GEMM with tf32 tensor cores (mma.sync.m16n8k8),
// norm scaling fused into the epilogue.
//   Per group g: out_g[256,128] = H_g[256,768] * W_g[768,128], scaled.
// Tile: BM=64, BN=128 (full K), BK=32. 128 threads, 2x2 warps, 32x64/warp.
// ---------------------------------------------------------------------------
#define BM 64
#define BN 128
#define BK 32
#define A_STRIDE 36      // 32 + 4 pad: conflict-free fragment LDS
#define B_STRIDE 136     // 128 + 8 pad: conflict-free fragment LDS

__device__ __forceinline__ uint32_t f2tf32(float f) {
    uint32_t u;
    asm("cvt.rna.tf32.f32 %0, %1;" : "=r"(u) : "f"(f));
    return u;
}

__global__ __launch_bounds__(128, 4)
void groupfc_gemm(const float* __restrict__ h,
                  const float* __restrict__ w,
                  float* __restrict__ out) {
    __shared__ __align__(16) float sA[BM * A_STRIDE];  //  9216 B
    __shared__ __align__(16) float sB[BK * B_STRIDE];  // 17408 B

    const int g  = blockIdx.y;
    const int m0 = blockIdx.x * BM;
    const int tid  = threadIdx.x;
    const int warp = tid >> 5;
    const int lane = tid & 31;
    const int gid  = lane >> 2;     // 0..7
    const int tig  = lane & 3;      // 0..3
    const int wm   = warp >> 1;     // 0..1 : rows wm*32 .. +32
    const int wn   = warp & 1;      // 0..1 : cols wn*64 .. +64

    // h row b lives at h + ((b*G + g)*D); row stride between b's = G*D
    const float* hbase = h + ((size_t)m0 * G_SZ + (size_t)g) * D_SZ;
    const float* wgrp  = w + (size_t)g * D_SZ * K_SZ;

    float acc[2][8][4];
#pragma unroll
    for (int mf = 0; mf < 2; mf++)
#pragma unroll
        for (int nf = 0; nf < 8; nf++)
#pragma unroll
            for (int q = 0; q < 4; q++) acc[mf][nf][q] = 0.f;

    for (int k0 = 0; k0 < D_SZ; k0 += BK) {
        // --- stage A tile: 64 rows x 32 cols (512 float4, 4 per thread) ---
#pragma unroll
        for (int j = 0; j < 4; j++) {
            int i   = tid + j * 128;
            int row = i >> 3;       // 0..63
            int c4  = i & 7;        // 0..7 -> cols c4*4 .. +4
            float4 v = *reinterpret_cast<const float4*>(
                hbase + (size_t)row * ((size_t)G_SZ * D_SZ) + k0 + c4 * 4);
            reinterpret_cast<float4*>(sA)[row * (A_STRIDE / 4) + c4] = v;
        }
        // --- stage B tile: 32 rows(d) x 128 cols(k) (1024 float4, 8/thread) ---
#pragma unroll
        for (int j = 0; j < 8; j++) {
            int i   = tid + j * 128;
            int row = i >> 5;       // 0..31
            int c4  = i & 31;       // 0..31 -> cols c4*4 .. +4
            float4 v = *reinterpret_cast<const float4*>(
                wgrp + (size_t)(k0 + row) * K_SZ + c4 * 4);
            reinterpret_cast<float4*>(sB)[row * (B_STRIDE / 4) + c4] = v;
        }
        __syncthreads();

#pragma unroll
        for (int kk = 0; kk < BK; kk += 8) {
            uint32_t af[2][4];
            uint32_t bf[8][2];
#pragma unroll
            for (int mf = 0; mf < 2; mf++) {
                int ra = wm * 32 + mf * 16 + gid;
                af[mf][0] = f2tf32(sA[ra       * A_STRIDE + kk + tig]);
                af[mf][1] = f2tf32(sA[(ra + 8) * A_STRIDE + kk + tig]);
                af[mf][2] = f2tf32(sA[ra       * A_STRIDE + kk + tig + 4]);
                af[mf][3] = f2tf32(sA[(ra + 8) * A_STRIDE + kk + tig + 4]);
            }
#pragma unroll
            for (int nf = 0; nf < 8; nf++) {
                int cb = wn * 64 + nf * 8 + gid;
                bf[nf][0] = f2tf32(sB[(kk + tig)     * B_STRIDE + cb]);
                bf[nf][1] = f2tf32(sB[(kk + tig + 4) * B_STRIDE + cb]);
            }
#pragma unroll
            for (int mf = 0; mf < 2; mf++)
#pragma unroll
                for (int nf = 0; nf < 8; nf++) {
                    asm volatile(
                        "mma.sync.aligned.m16n8k8.row.col.f32.tf32.tf32.f32 "
                        "{%0,%1,%2,%3}, {%4,%5,%6,%7}, {%8,%9}, {%0,%1,%2,%3};"
                        : "+f"(acc[mf][nf][0]), "+f"(acc[mf][nf][1]),
                          "+f"(acc[mf][nf][2]), "+f"(acc[mf][nf][3])
                        : "r"(af[mf][0]), "r"(af[mf][1]),
                          "r"(af[mf][2]), "r"(af[mf][3]),
                          "r"(bf[nf][0]), "r"(bf[nf][1]));
                }
        }
        __syncthreads();
    }

    // --- epilogue: scale by 1/(||h_row|| * ||w_col||) and store ---
#pragma unroll
    for (int mf = 0; mf < 2; mf++) {
        int b0 = m0 + wm * 32 + mf * 16 + gid;       // global batch index
        float rh0 = g_rinvH[b0 * G_SZ + g];
        float rh1 = g_rinvH[(b0 + 8) * G_SZ + g];
        float* o0 = out + ((size_t)b0 * G_SZ + g) * K_SZ;
        float* o1 = o0 + (size_t)8 * G_SZ * K_SZ;
#pragma unroll
        for (int nf = 0; nf < 8; nf++) {
            int c = wn * 64 + nf * 8 + tig * 2;
            float rw0 = g_rinvW[g * K_SZ + c];
            float rw1 = g_rinvW[g * K_SZ + c + 1];
            float2 v0 = make_float2(acc[mf][nf][0] * rh0 * rw0,
                                    acc[mf][nf][1] * rh0 * rw1);
            float2 v1 = make_float2(acc[mf][nf][2] * rh1 * rw0,
                                    acc[mf][nf][3] * rh1 * rw1);
            *reinterpret_cast<float2*>(o0 + c) = v0;
            *reinterpret_cast<float2*>(o1 + c) = v1;
        }
    }
}

// ---------------------------------------------------------------------------
// Launch: norms (warm L2) then grouped GEMM. All in default stream, ordered.
// ---------------------------------------------------------------------------
extern "C" void kernel_launch(void* const* d_in, const int* in_sizes, int n_in,
                              void* d_out, int out_size) {
    const float* h = (const float*)d_in[0];              // [B,G,D]
    const float* w = (const float*)d_in[1];              // [G,D,K]
    float* out     = (float*)d_out;                      // [B,G,K]
    (void)in_sizes; (void)n_in; (void)out_size;

    hnorm_kernel<<<(B_SZ * G_SZ) / 8, 256>>>(h);         // 8 warps/block
    wnorm_kernel<<<G_SZ, 512>>>(w);
    groupfc_gemm<<<dim3(B_SZ / BM, G_SZ), 128>>>(h, w, out);
}

// round 7
// speedup vs baseline: 1.5135x; 1.5135x over previous
#include <cuda_runtime.h>
#include <cstdint>

// GroupFC: h[B,G,D], W[G,D,K], out[B,G,K] with L2-normalization on D for both.
#define B_SZ 256
#define G_SZ 100
#define D_SZ 768
#define K_SZ 128

#define BM 64
#define BN 128
#define BK 32
#define NTILE (D_SZ / BK)            // 24
#define A_STRIDE 36                  // 32+4 pad: conflict-free fragment LDS
#define B_STRIDE 136                 // 128+8 pad: conflict-free fragment LDS
#define SA_STAGE (BM * A_STRIDE)     // 2304 floats
#define SB_STAGE (BK * B_STRIDE)     // 4352 floats
#define SMEM_FLOATS (2 * SA_STAGE + 2 * SB_STAGE + BM + BN)   // 13504
#define SMEM_BYTES (SMEM_FLOATS * 4)                          // 54016

__device__ __forceinline__ uint32_t f2tf32(float f) {
    uint32_t u;
    asm("cvt.rna.tf32.f32 %0, %1;" : "=r"(u) : "f"(f));
    return u;
}

__device__ __forceinline__ void cp16(uint32_t saddr, const float* gaddr) {
    asm volatile("cp.async.cg.shared.global [%0], [%1], 16;"
                 :: "r"(saddr), "l"(gaddr));
}

__global__ __launch_bounds__(128, 3)
void groupfc_fused(const float* __restrict__ h,
                   const float* __restrict__ w,
                   float* __restrict__ out) {
    extern __shared__ float smem[];
    float* sA    = smem;                     // 2 stages of [BM][A_STRIDE], tf32 bits
    float* sB    = smem + 2 * SA_STAGE;      // 2 stages of [BK][B_STRIDE], raw fp32
    float* hsumS = sB + 2 * SB_STAGE;        // [BM]  sum of h^2 per local row
    float* wsumS = hsumS + BM;               // [BN]  sum of w^2 per column

    const int g    = blockIdx.y;
    const int m0   = blockIdx.x * BM;
    const int tid  = threadIdx.x;
    const int lane = tid & 31;
    const int warp = tid >> 5;
    const int gid  = lane >> 2;              // 0..7
    const int tig  = lane & 3;               // 0..3
    const int wm   = warp >> 1;              // 0..1 (m half)
    const int wn   = warp & 1;               // 0..1 (n half)

    const float* hbase = h + ((size_t)m0 * G_SZ + (size_t)g) * D_SZ;
    const float* wgrp  = w + (size_t)g * D_SZ * K_SZ;
    const size_t hstride = (size_t)G_SZ * D_SZ;   // between consecutive b rows

    const int arow = tid >> 3;               // 0..15 (A stage rows arow + 16j)
    const int ac4  = tid & 7;                // A col group of 4
    const int brow = tid >> 5;               // 0..3  (B stage rows brow + 4j)
    const int bc4  = tid & 31;               // B col group of 4

    const uint32_t sB_base = (uint32_t)__cvta_generic_to_shared(sB);

    float acc[2][8][4];
#pragma unroll
    for (int mf = 0; mf < 2; mf++)
#pragma unroll
        for (int nf = 0; nf < 8; nf++)
#pragma unroll
            for (int q = 0; q < 4; q++) acc[mf][nf][q] = 0.f;

    float asq[4] = {0.f, 0.f, 0.f, 0.f};
    float wsq[8] = {0.f, 0.f, 0.f, 0.f, 0.f, 0.f, 0.f, 0.f};
    float4 rA[4];

    // ---- helpers ----
    auto ldgA = [&](int t) {                 // gmem -> regs, fused sum-of-squares
#pragma unroll
        for (int j = 0; j < 4; j++) {
            rA[j] = *reinterpret_cast<const float4*>(
                hbase + (size_t)(arow + j * 16) * hstride + t * BK + ac4 * 4);
            asq[j] = fmaf(rA[j].x, rA[j].x,
                     fmaf(rA[j].y, rA[j].y,
                     fmaf(rA[j].z, rA[j].z,
                     fmaf(rA[j].w, rA[j].w, asq[j]))));
        }
    };
    auto stsA = [&](int s) {                 // regs -> smem, converted to tf32
        float* dst = sA + s * SA_STAGE;
#pragma unroll
        for (int j = 0; j < 4; j++) {
            uint4 u;
            u.x = f2tf32(rA[j].x); u.y = f2tf32(rA[j].y);
            u.z = f2tf32(rA[j].z); u.w = f2tf32(rA[j].w);
            *reinterpret_cast<uint4*>(dst + (arow + j * 16) * A_STRIDE + ac4 * 4) = u;
        }
    };
    auto cpB = [&](int t, int s) {           // gmem -> smem via cp.async
        uint32_t dst = sB_base + (uint32_t)(s * SB_STAGE) * 4u;
#pragma unroll
        for (int j = 0; j < 8; j++) {
            int row = brow + j * 4;
            cp16(dst + (uint32_t)(row * B_STRIDE + bc4 * 4) * 4u,
                 wgrp + (size_t)(t * BK + row) * K_SZ + bc4 * 4);
        }
        asm volatile("cp.async.commit_group;");
    };
    auto compute = [&](int s) {
        const float* cA = sA + s * SA_STAGE;
        const float* cB = sB + s * SB_STAGE;
#pragma unroll
        for (int kk = 0; kk < BK; kk += 8) {
            uint32_t af[2][4], bf[8][2];
#pragma unroll
            for (int mf = 0; mf < 2; mf++) {
                const float* p = cA + (wm * 32 + mf * 16 + gid) * A_STRIDE + kk + tig;
                af[mf][0] = __float_as_uint(p[0]);
                af[mf][1] = __float_as_uint(p[8 * A_STRIDE]);
                af[mf][2] = __float_as_uint(p[4]);
                af[mf][3] = __float_as_uint(p[8 * A_STRIDE + 4]);
            }
#pragma unroll
            for (int nf = 0; nf < 8; nf++) {
                int cb = wn * 64 + nf * 8 + gid;
                bf[nf][0] = __float_as_uint(cB[(kk + tig) * B_STRIDE + cb]);
                bf[nf][1] = __float_as_uint(cB[(kk + tig + 4) * B_STRIDE + cb]);
            }
            if (wm == 0) {                   // each B element read once by wm=0 pair
#pragma unroll
                for (int nf = 0; nf < 8; nf++) {
                    float b0 = __uint_as_float(bf[nf][0]);
                    float b1 = __uint_as_float(bf[nf][1]);
                    wsq[nf] = fmaf(b0, b0, fmaf(b1, b1, wsq[nf]));
                }
            }
#pragma unroll
            for (int mf = 0; mf < 2; mf++)
#pragma unroll
                for (int nf = 0; nf < 8; nf++) {
                    asm volatile(
                        "mma.sync.aligned.m16n8k8.row.col.f32.tf32.tf32.f32 "
                        "{%0,%1,%2,%3}, {%4,%5,%6,%7}, {%8,%9}, {%0,%1,%2,%3};"
                        : "+f"(acc[mf][nf][0]), "+f"(acc[mf][nf][1]),
                          "+f"(acc[mf][nf][2]), "+f"(acc[mf][nf][3])
                        : "r"(af[mf][0]), "r"(af[mf][1]),
                          "r"(af[mf][2]), "r"(af[mf][3]),
                          "r"(bf[nf][0]), "r"(bf[nf][1]));
                }
        }
    };

    // ---- prologue: stage tile 0 ----
    ldgA(0);
    cpB(0, 0);
    stsA(0);

    // ---- pipelined mainloop: one __syncthreads per tile ----
    int cur = 0;
    for (int t = 0; t < NTILE; t++) {
        int nxt = cur ^ 1;
        if (t + 1 < NTILE) {
            ldgA(t + 1);
            cpB(t + 1, nxt);
            asm volatile("cp.async.wait_group 1;");
        } else {
            asm volatile("cp.async.wait_group 0;");
        }
        __syncthreads();
        compute(cur);
        if (t + 1 < NTILE) stsA(nxt);
        cur = nxt;
    }

    // ---- norm reductions ----
#pragma unroll
    for (int j = 0; j < 4; j++) {            // 8 threads share each h row
        float s = asq[j];
        s += __shfl_xor_sync(0xffffffffu, s, 1);
        s += __shfl_xor_sync(0xffffffffu, s, 2);
        s += __shfl_xor_sync(0xffffffffu, s, 4);
        if ((lane & 7) == 0) hsumS[arow + j * 16] = s;
    }
    if (wm == 0) {                           // 4 tig lanes share each w column
#pragma unroll
        for (int nf = 0; nf < 8; nf++) {
            float s = wsq[nf];
            s += __shfl_xor_sync(0xffffffffu, s, 1);
            s += __shfl_xor_sync(0xffffffffu, s, 2);
            if (tig == 0) wsumS[wn * 64 + nf * 8 + gid] = s;
        }
    }
    __syncthreads();

    // ---- epilogue: scale by 1/(||h_row|| * ||w_col||), store ----
    float rwv[8][2];
#pragma unroll
    for (int nf = 0; nf < 8; nf++) {
        int c = wn * 64 + nf * 8 + tig * 2;
        rwv[nf][0] = 1.0f / fmaxf(sqrtf(wsumS[c]), 1e-12f);
        rwv[nf][1] = 1.0f / fmaxf(sqrtf(wsumS[c + 1]), 1e-12f);
    }
#pragma unroll
    for (int mf = 0; mf < 2; mf++) {
        int r  = wm * 32 + mf * 16 + gid;
        int b0 = m0 + r;
        float rh0 = 1.0f / fmaxf(sqrtf(hsumS[r]), 1e-12f);
        float rh1 = 1.0f / fmaxf(sqrtf(hsumS[r + 8]), 1e-12f);
        float* o0 = out + ((size_t)b0 * G_SZ + g) * K_SZ;
        float* o1 = o0 + (size_t)8 * G_SZ * K_SZ;
#pragma unroll
        for (int nf = 0; nf < 8; nf++) {
            int c = wn * 64 + nf * 8 + tig * 2;
            float2 v0 = make_float2(acc[mf][nf][0] * rh0 * rwv[nf][0],
                                    acc[mf][nf][1] * rh0 * rwv[nf][1]);
            float2 v1 = make_float2(acc[mf][nf][2] * rh1 * rwv[nf][0],
                                    acc[mf][nf][3] * rh1 * rwv[nf][1]);
            *reinterpret_cast<float2*>(o0 + c) = v0;
            *reinterpret_cast<float2*>(o1 + c) = v1;
        }
    }
}

extern "C" void kernel_launch(void* const* d_in, const int* in_sizes, int n_in,
                              void* d_out, int out_size) {
    const float* h = (const float*)d_in[0];   // [B,G,D]
    const float* w = (const float*)d_in[1];   // [G,D,K]
    float* out     = (float*)d_out;           // [B,G,K]
    (void)in_sizes; (void)n_in; (void)out_size;

    cudaFuncSetAttribute(groupfc_fused,
                         cudaFuncAttributeMaxDynamicSharedMemorySize, SMEM_BYTES);
    groupfc_fused<<<dim3(B_SZ / BM, G_SZ), 128, SMEM_BYTES>>>(h, w, out);
}